// round 14
// baseline (speedup 1.0000x reference)
#include <cuda_runtime.h>

// ---------------- problem constants (fixed shapes) ----------------
#define Bc 2
#define Nc 50000
#define Cc 15
#define PAIRS (Bc*Cc)          // 30
#define CS 4                   // cluster size (CTAs per (b,c) pair)
#define NPER (Nc/CS)           // 12500 candidates per CTA
#define TH 512
#define CPT 25                 // 25*512 = 12800 >= 12500
#define MAXDET 300
#define NEGV (-1e9f)
#define NK (Cc*MAXDET)         // 4500

#define DYN_BYTES (CPT*TH*16)  // 204800 B box cache
#define FIN_BYTES (NK*12)      // keys (8B) + idx (4B)

typedef unsigned long long u64;

// scratch (no allocations allowed -> __device__ globals)
__device__ int   g_pick_idx[PAIRS*MAXDET];
__device__ float g_pick_score[PAIRS*MAXDET];

// pack (score, index) into a u64 so that max() == (higher score, then LOWER index)
__device__ __forceinline__ u64 packkey(float s, unsigned int gidx){
    unsigned int sb = __float_as_uint(s);
    sb = (sb & 0x80000000u) ? ~sb : (sb | 0x80000000u);   // monotone float->uint
    return ((u64)sb << 32) | (unsigned int)(~gidx);
}
__device__ __forceinline__ float unpackscore(u64 k){
    unsigned int sb = (unsigned int)(k >> 32);
    return (sb & 0x80000000u) ? __uint_as_float(sb ^ 0x80000000u)
                              : __uint_as_float(~sb);
}
__device__ __forceinline__ void top2ins(u64 kk, u64 &m1, u64 &m2){
    if (kk > m1){ m2 = m1; m1 = kk; }
    else if (kk > m2){ m2 = kk; }
}
__device__ __forceinline__ void warp_top2(u64 &m1, u64 &m2){
    #pragma unroll
    for (int o = 16; o; o >>= 1){
        u64 o1 = __shfl_xor_sync(0xFFFFFFFFu, m1, o);
        u64 o2 = __shfl_xor_sync(0xFFFFFFFFu, m2, o);
        u64 hi = (m1 > o1) ? m1 : o1;
        u64 lo = (m1 > o1) ? o1 : m1;
        u64 mm = (m2 > o2) ? m2 : o2;
        m1 = hi;
        m2 = (lo > mm) ? lo : mm;
    }
}

extern __shared__ float4 s_boxes[];

__global__ void __cluster_dims__(CS,1,1) __launch_bounds__(TH,1)
nms_kernel(const float* __restrict__ boxes, const float* __restrict__ cls)
{
    __shared__ u64 s_w1[16], s_w2[16];
    __shared__ u64 s_key [2][CS][2];   // double-buffered cluster exchange
    __shared__ __align__(16) float4 s_pbox[2][CS][2];
    __shared__ u64 s_mbar[2];

    const int pair = blockIdx.x >> 2;
    const int rank = blockIdx.x & 3;
    const int b = pair / Cc;
    const int c = pair % Cc;
    const int base = rank * NPER;
    const int t = threadIdx.x;

    const float4* gbox = reinterpret_cast<const float4*>(boxes) + (size_t)b * Nc;

    if (t == 0){
        unsigned int m0 = (unsigned int)__cvta_generic_to_shared(&s_mbar[0]);
        unsigned int m1 = (unsigned int)__cvta_generic_to_shared(&s_mbar[1]);
        asm volatile("mbarrier.init.shared.b64 [%0], %1;" :: "r"(m0), "r"(CS) : "memory");
        asm volatile("mbarrier.init.shared.b64 [%0], %1;" :: "r"(m1), "r"(CS) : "memory");
    }

    // ---- load this CTA's boxes into SMEM (coalesced); zero OOB tail ----
    for (int i = t; i < NPER; i += TH) s_boxes[i] = gbox[base + i];
    for (int i = NPER + t; i < CPT*TH; i += TH) s_boxes[i] = make_float4(0.f,0.f,0.f,0.f);

    // ---- load + threshold scores into registers; cache (area + 1e-9) ----
    float sc[CPT], arp[CPT];
    #pragma unroll
    for (int k = 0; k < CPT; k++){
        int li = k*TH + t;
        float s = NEGV;
        if (li < NPER){
            float v = cls[((size_t)(b*Nc + base + li))*Cc + c];
            if (v > 0.05f) s = v;
        }
        sc[k] = s;
    }
    __syncthreads();
    #pragma unroll
    for (int k = 0; k < CPT; k++){
        float4 bx = s_boxes[k*TH + t];
        arp[k] = (bx.z - bx.x) * (bx.w - bx.y) + 1e-9f;   // fast-path only
    }

    // cluster sync: mbarrier inits visible cluster-wide before any remote arrive
    asm volatile("barrier.cluster.arrive.aligned;" ::: "memory");
    asm volatile("barrier.cluster.wait.aligned;"   ::: "memory");

    // ---- initial per-thread top-2 + their slot ids ----
    u64 myM1 = 0ull, myM2 = 0ull;
    #pragma unroll
    for (int k = 0; k < CPT; k++)
        top2ins(packkey(sc[k], (unsigned)(base + k*TH + t)), myM1, myM2);
    int k1m = (int)(((~(unsigned int)myM1) - (unsigned)base) >> 9);
    int k2m = (int)(((~(unsigned int)myM2) - (unsigned)base) >> 9);

    // exact IoU test (reference formula, IEEE div): iou(P,B) > 0.5
    auto iou_gt = [](float4 P, float pa, float4 B) -> bool {
        float ab = (B.z - B.x) * (B.w - B.y);
        float y1 = fmaxf(P.x, B.x), x1 = fmaxf(P.y, B.y);
        float y2 = fminf(P.z, B.z), x2 = fminf(P.w, B.w);
        float inter = fmaxf(y2 - y1, 0.f) * fmaxf(x2 - x1, 0.f);
        float denom = pa + ab - inter + 1e-9f;
        return __fdiv_rn(inter, denom) > 0.5f;
    };

    // ---- NMS rounds: 1 or 2 picks per round ----
    int det = 0, round = 0;
    while (det < MAXDET){
        const int pidx = round & 1;
        const unsigned par = (unsigned)((round >> 1) & 1);

        // CTA top-2 reduce
        u64 a1 = myM1, a2 = myM2;
        warp_top2(a1, a2);
        if ((t & 31) == 0){ s_w1[t >> 5] = a1; s_w2[t >> 5] = a2; }
        __syncthreads();
        if (t < 32){
            u64 c1 = (t < 16) ? s_w1[t] : 0ull;
            u64 c2 = (t < 16) ? s_w2[t] : 0ull;
            warp_top2(c1, c2);
            if (t < CS){
                unsigned int wloc1 = (~(unsigned int)c1) - (unsigned)base;
                unsigned int wloc2 = (~(unsigned int)c2) - (unsigned)base;
                float4 wb1 = s_boxes[wloc1];
                float4 wb2 = s_boxes[wloc2];
                u64 x01, x23, y01, y23;
                asm("mov.b64 %0, {%1,%2};" : "=l"(x01) : "f"(wb1.x), "f"(wb1.y));
                asm("mov.b64 %0, {%1,%2};" : "=l"(x23) : "f"(wb1.z), "f"(wb1.w));
                asm("mov.b64 %0, {%1,%2};" : "=l"(y01) : "f"(wb2.x), "f"(wb2.y));
                asm("mov.b64 %0, {%1,%2};" : "=l"(y23) : "f"(wb2.z), "f"(wb2.w));
                unsigned int lkey = (unsigned int)__cvta_generic_to_shared(&s_key [pidx][rank][0]);
                unsigned int lbox = (unsigned int)__cvta_generic_to_shared(&s_pbox[pidx][rank][0]);
                unsigned int lmb  = (unsigned int)__cvta_generic_to_shared(&s_mbar[pidx]);
                unsigned int rk, rb, rm;
                asm("mapa.shared::cluster.u32 %0, %1, %2;" : "=r"(rk) : "r"(lkey), "r"(t));
                asm("mapa.shared::cluster.u32 %0, %1, %2;" : "=r"(rb) : "r"(lbox), "r"(t));
                asm("mapa.shared::cluster.u32 %0, %1, %2;" : "=r"(rm) : "r"(lmb),  "r"(t));
                asm volatile("st.shared::cluster.u64 [%0], %1;"    :: "r"(rk), "l"(c1)  : "memory");
                asm volatile("st.shared::cluster.u64 [%0+8], %1;"  :: "r"(rk), "l"(c2)  : "memory");
                asm volatile("st.shared::cluster.u64 [%0], %1;"    :: "r"(rb), "l"(x01) : "memory");
                asm volatile("st.shared::cluster.u64 [%0+8], %1;"  :: "r"(rb), "l"(x23) : "memory");
                asm volatile("st.shared::cluster.u64 [%0+16], %1;" :: "r"(rb), "l"(y01) : "memory");
                asm volatile("st.shared::cluster.u64 [%0+24], %1;" :: "r"(rb), "l"(y23) : "memory");
                asm volatile("mbarrier.arrive.release.cluster.shared::cluster.b64 _, [%0];" :: "r"(rm) : "memory");
            }
        }
        // wait for all 4 CTAs (acquire orders remote stores)
        {
            unsigned int mloc = (unsigned int)__cvta_generic_to_shared(&s_mbar[pidx]);
            unsigned int done = 0;
            while (!done){
                asm volatile(
                    "{\n\t.reg .pred p;\n\t"
                    "mbarrier.try_wait.parity.acquire.cluster.shared::cta.b64 p, [%1], %2, 0x989680;\n\t"
                    "selp.b32 %0, 1, 0, p;\n\t}"
                    : "=r"(done) : "r"(mloc), "r"(par) : "memory");
            }
        }

        // global top-2 merge (identical on every thread of every CTA)
        u64 M1 = s_key[pidx][0][0]; int r1 = 0;
        #pragma unroll
        for (int r = 1; r < CS; r++){
            u64 v = s_key[pidx][r][0];
            if (v > M1){ M1 = v; r1 = r; }
        }
        u64 M2 = 0ull; int r2 = 0;
        #pragma unroll
        for (int r = 0; r < CS; r++){
            u64 v = (r == r1) ? s_key[pidx][r][1] : s_key[pidx][r][0];
            if (v > M2){ M2 = v; r2 = r; }
        }
        const int slot2 = (r2 == r1) ? 1 : 0;
        float4 B1 = s_pbox[pidx][r1][0];
        float4 B2 = s_pbox[pidx][r2][slot2];

        const unsigned int widx1 = ~((unsigned int)M1);
        const float pa1 = (B1.z - B1.x) * (B1.w - B1.y);
        const float score2 = unpackscore(M2);

        // dual-pick decision (exact IEEE IoU between the two winners)
        bool dual = false;
        float pa2 = pa1;
        if (score2 != NEGV && det + 1 < MAXDET){
            float a2f = (B2.z - B2.x) * (B2.w - B2.y);
            if (!iou_gt(B1, pa1, B2)){ dual = true; pa2 = a2f; }
        }
        const unsigned int widx2 = dual ? ~((unsigned int)M2) : widx1;

        if (rank == 0 && t == 0){
            g_pick_idx  [pair*MAXDET + det] = (int)widx1;
            g_pick_score[pair*MAXDET + det] = unpackscore(M1);
            if (dual){
                g_pick_idx  [pair*MAXDET + det + 1] = (int)widx2;
                g_pick_score[pair*MAXDET + det + 1] = score2;
            }
        }
        if (!dual) B2 = B1;

        // per-thread winner-slot ids (constant-compare vs k)
        const unsigned int wl1 = widx1 - (unsigned)base;
        const int W1 = ((wl1 & (TH-1)) == (unsigned)t) ? (int)(wl1 >> 9) : -1;
        int W2 = -1;
        if (dual){
            unsigned int wl2 = widx2 - (unsigned)base;
            W2 = ((wl2 & (TH-1)) == (unsigned)t) ? (int)(wl2 >> 9) : -1;
        }

        // ---- lean suppress pass: conservative band via 3*inter vs pa+ar+1e-9 ----
        // ab: certainly iou>0.5; bl: certainly iou<=0.5; margins 2e-4 >> fp error.
        unsigned band1 = 0, band2 = 0;
        bool lost = false;
        if (dual){
            #pragma unroll
            for (int k = 0; k < CPT; k++){
                float s = sc[k];
                bool alive = (s != NEGV);
                float4 bx = s_boxes[k*TH + t];
                float y1 = fmaxf(B1.x, bx.x), x1 = fmaxf(B1.y, bx.y);
                float y2 = fminf(B1.z, bx.z), x2 = fminf(B1.w, bx.w);
                float in1 = fmaxf(y2 - y1, 0.f) * fmaxf(x2 - x1, 0.f);
                float S1 = pa1 + arp[k];
                bool ab1 = (in1 * 3.0006f > S1);
                bool bl1 = (in1 * 2.9994f < S1);
                float z1 = fmaxf(B2.x, bx.x), w1 = fmaxf(B2.y, bx.y);
                float z2 = fminf(B2.z, bx.z), w2 = fminf(B2.w, bx.w);
                float in2 = fmaxf(z2 - z1, 0.f) * fmaxf(w2 - w1, 0.f);
                float S2 = pa2 + arp[k];
                bool ab2 = (in2 * 3.0006f > S2);
                bool bl2 = (in2 * 2.9994f < S2);
                band1 |= (alive && !ab1 && !bl1) ? (1u << k) : 0u;
                band2 |= (alive && !ab2 && !bl2) ? (1u << k) : 0u;
                bool supf = alive && (ab1 || ab2 || (k == W1) || (k == W2));
                if (supf){
                    sc[k] = NEGV;
                    lost = lost || (k == k1m) || (k == k2m);
                }
            }
        } else {
            #pragma unroll
            for (int k = 0; k < CPT; k++){
                float s = sc[k];
                bool alive = (s != NEGV);
                float4 bx = s_boxes[k*TH + t];
                float y1 = fmaxf(B1.x, bx.x), x1 = fmaxf(B1.y, bx.y);
                float y2 = fminf(B1.z, bx.z), x2 = fminf(B1.w, bx.w);
                float in1 = fmaxf(y2 - y1, 0.f) * fmaxf(x2 - x1, 0.f);
                float S1 = pa1 + arp[k];
                bool ab = (in1 * 3.0006f > S1);
                bool bl = (in1 * 2.9994f < S1);
                band1 |= (alive && !ab && !bl) ? (1u << k) : 0u;
                bool supf = alive && (ab || (k == W1));
                if (supf){
                    sc[k] = NEGV;
                    lost = lost || (k == k1m) || (k == k2m);
                }
            }
        }

        // rare exact-division fixup (warp-uniform outer branch)
        if (__any_sync(0xFFFFFFFFu, (band1 | band2) != 0)){
            unsigned bb = band1 | band2;
            #pragma unroll 1
            for (int k = 0; k < CPT; k++){
                if (bb & (1u << k)){
                    float4 bx = s_boxes[k*TH + t];
                    bool sup = false;
                    if (band1 & (1u << k)) sup |= iou_gt(B1, pa1, bx);
                    if (band2 & (1u << k)) sup |= iou_gt(B2, pa2, bx);
                    if (sup){
                        sc[k] = NEGV;
                        lost = lost || (k == k1m) || (k == k2m);
                    }
                }
            }
        }

        // recompute per-thread top-2 only if one of its top slots was suppressed
        if (__any_sync(0xFFFFFFFFu, lost)){
            u64 m1 = 0ull, m2 = 0ull;
            #pragma unroll
            for (int k = 0; k < CPT; k++)
                top2ins(packkey(sc[k], (unsigned)(base + k*TH + t)), m1, m2);
            myM1 = m1; myM2 = m2;
            k1m = (int)(((~(unsigned int)myM1) - (unsigned)base) >> 9);
            k2m = (int)(((~(unsigned int)myM2) - (unsigned)base) >> 9);
        }

        det += dual ? 2 : 1;
        round++;
    }

    // trailing sync so no CTA exits while peers may still address its SMEM
    asm volatile("barrier.cluster.arrive.aligned;" ::: "memory");
    asm volatile("barrier.cluster.wait.aligned;"   ::: "memory");
}

// ---------------- per-image top-300 via per-key global rank ----------------
extern __shared__ char f_dyn[];
__global__ void __launch_bounds__(512)
finalize_kernel(const float* __restrict__ boxes, float* __restrict__ out)
{
    u64* s_keys = reinterpret_cast<u64*>(f_dyn);
    int* s_idx = reinterpret_cast<int*>(f_dyn + NK*8);

    const int b = blockIdx.x;
    const int t = threadIdx.x;

    for (int i = t; i < NK; i += 512){
        s_keys[i] = packkey(g_pick_score[b*NK + i], (unsigned)i);
        s_idx[i]  = g_pick_idx[b*NK + i];
    }
    __syncthreads();

    const float4* gbox = reinterpret_cast<const float4*>(boxes) + (size_t)b * Nc;
    float4* obox   = reinterpret_cast<float4*>(out);
    float*  oscore = out + (size_t)Bc*MAXDET*4;
    float*  olab   = out + (size_t)Bc*MAXDET*5;

    for (int i = t; i < NK; i += 512){
        u64 my = s_keys[i];
        int rnk = 0;
        #pragma unroll
        for (int c = 0; c < Cc; c++){
            int lo = 0, hi = MAXDET;
            while (lo < hi){                       // 9 data-independent steps
                int mid = (lo + hi) >> 1;
                if (s_keys[c*MAXDET + mid] > my) lo = mid + 1; else hi = mid;
            }
            rnk += lo;
        }
        if (rnk < MAXDET){
            float s = unpackscore(my);
            bool valid = (s > (NEGV * 0.5f));
            unsigned int flat = ~((unsigned int)my);
            float4 bx = make_float4(-1.f, -1.f, -1.f, -1.f);
            float lab = -1.f;
            if (valid){
                bx  = gbox[s_idx[flat]];
                lab = (float)(flat / MAXDET);
            }
            obox  [b*MAXDET + rnk] = bx;
            oscore[b*MAXDET + rnk] = valid ? s : -1.f;
            olab  [b*MAXDET + rnk] = lab;
        }
    }
}

extern "C" void kernel_launch(void* const* d_in, const int* in_sizes, int n_in,
                              void* d_out, int out_size)
{
    const float* boxes = (const float*)d_in[0];
    const float* cls   = (const float*)d_in[1];
    if (n_in >= 2 && in_sizes[0] == Bc*Nc*Cc && in_sizes[1] == Bc*Nc*4){
        const float* tmp = boxes; boxes = cls; cls = tmp;
    }

    cudaFuncSetAttribute(nms_kernel, cudaFuncAttributeMaxDynamicSharedMemorySize, DYN_BYTES);
    cudaFuncSetAttribute(finalize_kernel, cudaFuncAttributeMaxDynamicSharedMemorySize, FIN_BYTES);

    nms_kernel<<<PAIRS*CS, TH, DYN_BYTES>>>(boxes, cls);
    finalize_kernel<<<Bc, 512, FIN_BYTES>>>(boxes, (float*)d_out);
}

// round 15
// speedup vs baseline: 1.1297x; 1.1297x over previous
#include <cuda_runtime.h>

// ---------------- problem constants (fixed shapes) ----------------
#define Bc 2
#define Nc 50000
#define Cc 15
#define PAIRS (Bc*Cc)          // 30
#define CS 4                   // cluster size (CTAs per (b,c) pair)
#define NPER (Nc/CS)           // 12500 candidates per CTA
#define TH 512
#define CPT 25                 // 25*512 = 12800 >= 12500
#define MAXDET 300
#define NEGV (-1e9f)
#define NK (Cc*MAXDET)         // 4500

#define DYN_BYTES (CPT*TH*16)  // 204800 B box cache

typedef unsigned long long u64;

// scratch (no allocations allowed -> __device__ globals)
__device__ int   g_pick_idx[PAIRS*MAXDET];
__device__ float g_pick_score[PAIRS*MAXDET];
__device__ int   g_rank[Bc*NK];

// pack (score, index) into a u64 so that max() == (higher score, then LOWER index)
__device__ __forceinline__ u64 packkey(float s, unsigned int gidx){
    unsigned int sb = __float_as_uint(s);
    sb = (sb & 0x80000000u) ? ~sb : (sb | 0x80000000u);   // monotone float->uint
    return ((u64)sb << 32) | (unsigned int)(~gidx);
}
__device__ __forceinline__ float unpackscore(u64 k){
    unsigned int sb = (unsigned int)(k >> 32);
    return (sb & 0x80000000u) ? __uint_as_float(sb ^ 0x80000000u)
                              : __uint_as_float(~sb);
}
__device__ __forceinline__ void top2ins(u64 kk, u64 &m1, u64 &m2){
    if (kk > m1){ m2 = m1; m1 = kk; }
    else if (kk > m2){ m2 = kk; }
}
__device__ __forceinline__ void warp_top2(u64 &m1, u64 &m2){
    #pragma unroll
    for (int o = 16; o; o >>= 1){
        u64 o1 = __shfl_xor_sync(0xFFFFFFFFu, m1, o);
        u64 o2 = __shfl_xor_sync(0xFFFFFFFFu, m2, o);
        u64 hi = (m1 > o1) ? m1 : o1;
        u64 lo = (m1 > o1) ? o1 : m1;
        u64 mm = (m2 > o2) ? m2 : o2;
        m1 = hi;
        m2 = (lo > mm) ? lo : mm;
    }
}

extern __shared__ float4 s_boxes[];

// =======================================================================
// nms_kernel — byte-identical to the R8 best (1059us); do not touch.
// =======================================================================
__global__ void __cluster_dims__(CS,1,1) __launch_bounds__(TH,1)
nms_kernel(const float* __restrict__ boxes, const float* __restrict__ cls)
{
    __shared__ u64 s_w1[16], s_w2[16];
    __shared__ u64 s_key [2][CS][2];   // double-buffered cluster exchange
    __shared__ __align__(16) float4 s_pbox[2][CS][2];
    __shared__ u64 s_mbar[2];

    const int pair = blockIdx.x >> 2;
    const int rank = blockIdx.x & 3;
    const int b = pair / Cc;
    const int c = pair % Cc;
    const int base = rank * NPER;
    const int t = threadIdx.x;

    const float4* gbox = reinterpret_cast<const float4*>(boxes) + (size_t)b * Nc;

    if (t == 0){
        unsigned int m0 = (unsigned int)__cvta_generic_to_shared(&s_mbar[0]);
        unsigned int m1 = (unsigned int)__cvta_generic_to_shared(&s_mbar[1]);
        asm volatile("mbarrier.init.shared.b64 [%0], %1;" :: "r"(m0), "r"(CS) : "memory");
        asm volatile("mbarrier.init.shared.b64 [%0], %1;" :: "r"(m1), "r"(CS) : "memory");
    }

    // ---- load this CTA's boxes into SMEM (coalesced) ----
    for (int i = t; i < NPER; i += TH) s_boxes[i] = gbox[base + i];

    // ---- load + threshold scores into registers; cache areas ----
    float sc[CPT], ar[CPT];
    #pragma unroll
    for (int k = 0; k < CPT; k++){
        int li = k*TH + t;
        float s = NEGV;
        if (li < NPER){
            float v = cls[((size_t)(b*Nc + base + li))*Cc + c];
            if (v > 0.05f) s = v;
        }
        sc[k] = s;
    }
    __syncthreads();
    #pragma unroll
    for (int k = 0; k < CPT; k++){
        int li = k*TH + t;
        float a = 0.f;
        if (li < NPER){ float4 bx = s_boxes[li]; a = (bx.z - bx.x) * (bx.w - bx.y); }
        ar[k] = a;
    }

    // cluster sync: mbarrier inits visible cluster-wide before any remote arrive
    asm volatile("barrier.cluster.arrive.aligned;" ::: "memory");
    asm volatile("barrier.cluster.wait.aligned;"   ::: "memory");

    // ---- initial per-thread top-2 ----
    u64 myM1 = 0ull, myM2 = 0ull;
    #pragma unroll
    for (int k = 0; k < CPT; k++)
        top2ins(packkey(sc[k], (unsigned)(base + k*TH + t)), myM1, myM2);

    // ---- NMS rounds: 1 or 2 picks per round ----
    int det = 0, round = 0;
    while (det < MAXDET){
        const int pidx = round & 1;
        const unsigned par = (unsigned)((round >> 1) & 1);

        // CTA top-2 reduce
        u64 a1 = myM1, a2 = myM2;
        warp_top2(a1, a2);
        if ((t & 31) == 0){ s_w1[t >> 5] = a1; s_w2[t >> 5] = a2; }
        __syncthreads();
        if (t < 32){
            u64 c1 = (t < 16) ? s_w1[t] : 0ull;
            u64 c2 = (t < 16) ? s_w2[t] : 0ull;
            warp_top2(c1, c2);
            if (t < CS){
                // lane r ships (k1,k2,box1,box2) to CTA r's slot[rank], then arrives there
                unsigned int wloc1 = (~(unsigned int)c1) - (unsigned)base;
                unsigned int wloc2 = (~(unsigned int)c2) - (unsigned)base;
                float4 wb1 = s_boxes[wloc1];
                float4 wb2 = s_boxes[wloc2];
                u64 x01, x23, y01, y23;
                asm("mov.b64 %0, {%1,%2};" : "=l"(x01) : "f"(wb1.x), "f"(wb1.y));
                asm("mov.b64 %0, {%1,%2};" : "=l"(x23) : "f"(wb1.z), "f"(wb1.w));
                asm("mov.b64 %0, {%1,%2};" : "=l"(y01) : "f"(wb2.x), "f"(wb2.y));
                asm("mov.b64 %0, {%1,%2};" : "=l"(y23) : "f"(wb2.z), "f"(wb2.w));
                unsigned int lkey = (unsigned int)__cvta_generic_to_shared(&s_key [pidx][rank][0]);
                unsigned int lbox = (unsigned int)__cvta_generic_to_shared(&s_pbox[pidx][rank][0]);
                unsigned int lmb  = (unsigned int)__cvta_generic_to_shared(&s_mbar[pidx]);
                unsigned int rk, rb, rm;
                asm("mapa.shared::cluster.u32 %0, %1, %2;" : "=r"(rk) : "r"(lkey), "r"(t));
                asm("mapa.shared::cluster.u32 %0, %1, %2;" : "=r"(rb) : "r"(lbox), "r"(t));
                asm("mapa.shared::cluster.u32 %0, %1, %2;" : "=r"(rm) : "r"(lmb),  "r"(t));
                asm volatile("st.shared::cluster.u64 [%0], %1;"    :: "r"(rk), "l"(c1)  : "memory");
                asm volatile("st.shared::cluster.u64 [%0+8], %1;"  :: "r"(rk), "l"(c2)  : "memory");
                asm volatile("st.shared::cluster.u64 [%0], %1;"    :: "r"(rb), "l"(x01) : "memory");
                asm volatile("st.shared::cluster.u64 [%0+8], %1;"  :: "r"(rb), "l"(x23) : "memory");
                asm volatile("st.shared::cluster.u64 [%0+16], %1;" :: "r"(rb), "l"(y01) : "memory");
                asm volatile("st.shared::cluster.u64 [%0+24], %1;" :: "r"(rb), "l"(y23) : "memory");
                asm volatile("mbarrier.arrive.release.cluster.shared::cluster.b64 _, [%0];" :: "r"(rm) : "memory");
            }
        }
        // wait for all 4 CTAs (acquire orders remote stores)
        {
            unsigned int mloc = (unsigned int)__cvta_generic_to_shared(&s_mbar[pidx]);
            unsigned int done = 0;
            while (!done){
                asm volatile(
                    "{\n\t.reg .pred p;\n\t"
                    "mbarrier.try_wait.parity.acquire.cluster.shared::cta.b64 p, [%1], %2, 0x989680;\n\t"
                    "selp.b32 %0, 1, 0, p;\n\t}"
                    : "=r"(done) : "r"(mloc), "r"(par) : "memory");
            }
        }

        // global top-2 merge (identical on every thread of every CTA)
        u64 M1 = s_key[pidx][0][0]; int r1 = 0;
        #pragma unroll
        for (int r = 1; r < CS; r++){
            u64 v = s_key[pidx][r][0];
            if (v > M1){ M1 = v; r1 = r; }
        }
        u64 M2 = 0ull; int r2 = 0;
        #pragma unroll
        for (int r = 0; r < CS; r++){
            u64 v = (r == r1) ? s_key[pidx][r][1] : s_key[pidx][r][0];
            if (v > M2){ M2 = v; r2 = r; }
        }
        const int slot2 = (r2 == r1) ? 1 : 0;
        float4 B1 = s_pbox[pidx][r1][0];
        float4 B2 = s_pbox[pidx][r2][slot2];

        const unsigned int widx1 = ~((unsigned int)M1);
        const float pa1 = (B1.z - B1.x) * (B1.w - B1.y);
        const float score2 = unpackscore(M2);

        // dual-pick decision: K2 is provably the next sequential pick iff alive
        // and not suppressed by K1 (exact IEEE IoU, same formula as the scan).
        bool dual = false;
        float pa2 = pa1;
        if (score2 != NEGV && det + 1 < MAXDET){
            float a2f = (B2.z - B2.x) * (B2.w - B2.y);
            float y1 = fmaxf(B1.x, B2.x);
            float x1 = fmaxf(B1.y, B2.y);
            float y2 = fminf(B1.z, B2.z);
            float x2 = fminf(B1.w, B2.w);
            float inter = fmaxf(y2 - y1, 0.f) * fmaxf(x2 - x1, 0.f);
            float denom = pa1 + a2f - inter + 1e-9f;
            if (!(__fdiv_rn(inter, denom) > 0.5f)){ dual = true; pa2 = a2f; }
        }
        const unsigned int widx2 = dual ? ~((unsigned int)M2) : widx1;

        if (rank == 0 && t == 0){
            g_pick_idx  [pair*MAXDET + det] = (int)widx1;
            g_pick_score[pair*MAXDET + det] = unpackscore(M1);
            if (dual){
                g_pick_idx  [pair*MAXDET + det + 1] = (int)widx2;
                g_pick_score[pair*MAXDET + det + 1] = score2;
            }
        }
        if (!dual) B2 = B1;

        // per-thread winner-slot ids (constant-compare vs k in the unrolled loop)
        const unsigned int wl1 = widx1 - (unsigned)base;
        const int myWl1 = ((wl1 & (TH-1)) == (unsigned)t) ? (int)(wl1 >> 9) : -1;
        int myWl2 = -1;
        if (dual){
            unsigned int wl2 = widx2 - (unsigned)base;
            myWl2 = ((wl2 & (TH-1)) == (unsigned)t) ? (int)(wl2 >> 9) : -1;
        }

        // ---- suppress pass (1 or 2 pivots; cluster-uniform branch) ----
        unsigned band1 = 0, band2 = 0;
        if (dual){
            #pragma unroll
            for (int k = 0; k < CPT; k++){
                float s = sc[k];
                bool alive = (s != NEGV);
                float4 bx = make_float4(0.f,0.f,0.f,0.f);
                if (alive) bx = s_boxes[k*TH + t];
                float p1y1 = fmaxf(B1.x, bx.x), p1x1 = fmaxf(B1.y, bx.y);
                float p1y2 = fminf(B1.z, bx.z), p1x2 = fminf(B1.w, bx.w);
                float in1 = fmaxf(p1y2 - p1y1, 0.f) * fmaxf(p1x2 - p1x1, 0.f);
                float dn1 = pa1 + ar[k] - in1 + 1e-9f;
                float ii1 = in1 + in1;
                bool ab1 = (ii1 > 1.0001f * dn1);
                bool bl1 = (ii1 < 0.9999f * dn1);
                float p2y1 = fmaxf(B2.x, bx.x), p2x1 = fmaxf(B2.y, bx.y);
                float p2y2 = fminf(B2.z, bx.z), p2x2 = fminf(B2.w, bx.w);
                float in2 = fmaxf(p2y2 - p2y1, 0.f) * fmaxf(p2x2 - p2x1, 0.f);
                float dn2 = pa2 + ar[k] - in2 + 1e-9f;
                float ii2 = in2 + in2;
                bool ab2 = (ii2 > 1.0001f * dn2);
                bool bl2 = (ii2 < 0.9999f * dn2);
                band1 |= (alive && !ab1 && !bl1) ? (1u << k) : 0u;
                band2 |= (alive && !ab2 && !bl2) ? (1u << k) : 0u;
                bool supf = alive && (ab1 || ab2 || (k == myWl1) || (k == myWl2));
                sc[k] = supf ? NEGV : s;
            }
        } else {
            #pragma unroll
            for (int k = 0; k < CPT; k++){
                float s = sc[k];
                bool alive = (s != NEGV);
                float4 bx = make_float4(0.f,0.f,0.f,0.f);
                if (alive) bx = s_boxes[k*TH + t];
                float y1 = fmaxf(B1.x, bx.x), x1 = fmaxf(B1.y, bx.y);
                float y2 = fminf(B1.z, bx.z), x2 = fminf(B1.w, bx.w);
                float inter = fmaxf(y2 - y1, 0.f) * fmaxf(x2 - x1, 0.f);
                float denom = pa1 + ar[k] - inter + 1e-9f;
                float ii = inter + inter;
                bool ab = (ii > 1.0001f * denom);
                bool bl = (ii < 0.9999f * denom);
                band1 |= (alive && !ab && !bl) ? (1u << k) : 0u;
                bool supf = alive && (ab || (k == myWl1));
                sc[k] = supf ? NEGV : s;
            }
        }

        // rare exact-division fixup (warp-uniform outer branch)
        if (__any_sync(0xFFFFFFFFu, (band1 | band2) != 0)){
            unsigned bb = band1 | band2;
            #pragma unroll
            for (int k = 0; k < CPT; k++){
                if (bb & (1u << k)){
                    float4 bx = s_boxes[k*TH + t];
                    float ak = (bx.z - bx.x) * (bx.w - bx.y);
                    if (band1 & (1u << k)){
                        float y1 = fmaxf(B1.x, bx.x), x1 = fmaxf(B1.y, bx.y);
                        float y2 = fminf(B1.z, bx.z), x2 = fminf(B1.w, bx.w);
                        float inter = fmaxf(y2 - y1, 0.f) * fmaxf(x2 - x1, 0.f);
                        float denom = pa1 + ak - inter + 1e-9f;
                        if (__fdiv_rn(inter, denom) > 0.5f) sc[k] = NEGV;
                    }
                    if (band2 & (1u << k)){
                        float y1 = fmaxf(B2.x, bx.x), x1 = fmaxf(B2.y, bx.y);
                        float y2 = fminf(B2.z, bx.z), x2 = fminf(B2.w, bx.w);
                        float inter = fmaxf(y2 - y1, 0.f) * fmaxf(x2 - x1, 0.f);
                        float denom = pa2 + ak - inter + 1e-9f;
                        if (__fdiv_rn(inter, denom) > 0.5f) sc[k] = NEGV;
                    }
                }
            }
        }

        // fresh per-thread top-2 (registers only)
        {
            u64 m1 = 0ull, m2 = 0ull;
            #pragma unroll
            for (int k = 0; k < CPT; k++)
                top2ins(packkey(sc[k], (unsigned)(base + k*TH + t)), m1, m2);
            myM1 = m1; myM2 = m2;
        }

        det += dual ? 2 : 1;
        round++;
    }

    // trailing sync so no CTA exits while peers may still address its SMEM
    asm volatile("barrier.cluster.arrive.aligned;" ::: "memory");
    asm volatile("barrier.cluster.wait.aligned;"   ::: "memory");
}

// =======================================================================
// finalize, re-decomposed: zero_rank -> rank_kernel (30 blocks) -> out_kernel
// Same rank-by-counting semantics as the R8 finalize (validated rel_err=0);
// integer atomicAdd sums are order-independent -> deterministic.
// =======================================================================

__global__ void __launch_bounds__(512)
zero_rank_kernel()
{
    int i = blockIdx.x * blockDim.x + threadIdx.x;
    for (; i < Bc*NK; i += gridDim.x * blockDim.x) g_rank[i] = 0;
}

// one block per (b,c): count, for every key of image b, how many of class c's
// 300 keys are strictly greater; accumulate into g_rank.
__global__ void __launch_bounds__(512)
rank_kernel()
{
    __shared__ u64 s_k[MAXDET];
    const int b = blockIdx.x / Cc;
    const int c = blockIdx.x % Cc;
    const int t = threadIdx.x;

    if (t < MAXDET){
        int flat = c*MAXDET + t;
        s_k[t] = packkey(g_pick_score[b*NK + flat], (unsigned)flat);
    }
    __syncthreads();

    for (int i = t; i < NK; i += 512){
        u64 my = packkey(g_pick_score[b*NK + i], (unsigned)i);
        int lo = 0, hi = MAXDET;
        #pragma unroll
        for (int s = 0; s < 9; s++){               // 2^9=512 > 300, data-independent
            int mid = (lo + hi) >> 1;
            bool g = (mid < MAXDET) && (s_k[mid] > my);
            lo = g ? mid + 1 : lo;
            hi = g ? hi : mid;
        }
        if (lo > 0) atomicAdd(&g_rank[b*NK + i], lo);
    }
}

__global__ void __launch_bounds__(512)
out_kernel(const float* __restrict__ boxes, float* __restrict__ out)
{
    const int b = blockIdx.x;
    const int t = threadIdx.x;

    const float4* gbox = reinterpret_cast<const float4*>(boxes) + (size_t)b * Nc;
    float4* obox   = reinterpret_cast<float4*>(out);
    float*  oscore = out + (size_t)Bc*MAXDET*4;
    float*  olab   = out + (size_t)Bc*MAXDET*5;

    for (int i = t; i < NK; i += 512){
        int rnk = g_rank[b*NK + i];
        if (rnk < MAXDET){
            float s = g_pick_score[b*NK + i];
            bool valid = (s > (NEGV * 0.5f));
            float4 bx = make_float4(-1.f, -1.f, -1.f, -1.f);
            float lab = -1.f;
            if (valid){
                bx  = gbox[g_pick_idx[b*NK + i]];
                lab = (float)(i / MAXDET);
            }
            obox  [b*MAXDET + rnk] = bx;
            oscore[b*MAXDET + rnk] = valid ? s : -1.f;
            olab  [b*MAXDET + rnk] = lab;
        }
    }
}

extern "C" void kernel_launch(void* const* d_in, const int* in_sizes, int n_in,
                              void* d_out, int out_size)
{
    const float* boxes = (const float*)d_in[0];
    const float* cls   = (const float*)d_in[1];
    if (n_in >= 2 && in_sizes[0] == Bc*Nc*Cc && in_sizes[1] == Bc*Nc*4){
        const float* tmp = boxes; boxes = cls; cls = tmp;
    }

    cudaFuncSetAttribute(nms_kernel, cudaFuncAttributeMaxDynamicSharedMemorySize, DYN_BYTES);

    zero_rank_kernel<<<4, 512>>>();                       // before nms; hidden cost
    nms_kernel<<<PAIRS*CS, TH, DYN_BYTES>>>(boxes, cls);
    rank_kernel<<<PAIRS, 512>>>();
    out_kernel<<<Bc, 512>>>(boxes, (float*)d_out);
}